// round 5
// baseline (speedup 1.0000x reference)
#include <cuda_runtime.h>
#include <cuda_bf16.h>
#include <cstdint>

// Problem constants
#define BATCH 16
#define HH 56
#define WW 56
#define NN (HH * WW)          // 3136
#define CC 384
#define C3 (3 * CC)           // 1152
#define NHEADS 12
#define HD 32
#define WSZ 7
#define WIN 49
#define MROWS (BATCH * NN)    // 50176

// GEMM tiling
#define BM 128
#define BN 128
#define BK 16
#define SROW 20                   // smem row stride (floats); 80B, ldmatrix conflict-free
#define ABUF (BM * SROW * 4)      // 10240 per A (or B) buffer
#define STAGE_BYTES (2 * ABUF)    // 20480
#define NSTAGE 5

// Scratch (allocation-free rule: __device__ globals)
__device__ float g_qkv[(size_t)MROWS * C3];     // 231 MB
__device__ float g_y[(size_t)MROWS * CC];       // 77 MB
__device__ float g_xr[(size_t)MROWS * CC];      // 77 MB (tf32-rounded x)
__device__ float g_wt1[(size_t)C3 * CC];        // w_qkv transposed [1152][384]
__device__ float g_wt2[(size_t)CC * CC];        // w_proj transposed [384][384]

// ---------------------------------------------------------------------------
__device__ __forceinline__ uint32_t smem_u32(const void* p) {
    uint32_t a;
    asm("{ .reg .u64 t; cvta.to.shared.u64 t, %1; cvt.u32.u64 %0, t; }" : "=r"(a) : "l"(p));
    return a;
}
__device__ __forceinline__ void cp_async16(uint32_t saddr, const void* gaddr) {
    asm volatile("cp.async.cg.shared.global [%0], [%1], 16;" :: "r"(saddr), "l"(gaddr));
}
template <int N>
__device__ __forceinline__ void cp_wait() {
    asm volatile("cp.async.wait_group %0;" :: "n"(N) : "memory");
}
__device__ __forceinline__ float round_tf32(float f) {
    uint32_t u;
    asm("cvt.rna.tf32.f32 %0, %1;" : "=r"(u) : "f"(f));
    return __uint_as_float(u);
}
__device__ __forceinline__ void mma_tf32(float c[4], const uint32_t a[4],
                                         uint32_t b0, uint32_t b1) {
    asm volatile(
        "mma.sync.aligned.m16n8k8.row.col.f32.tf32.tf32.f32 "
        "{%0,%1,%2,%3}, {%4,%5,%6,%7}, {%8,%9}, {%0,%1,%2,%3};"
        : "+f"(c[0]), "+f"(c[1]), "+f"(c[2]), "+f"(c[3])
        : "r"(a[0]), "r"(a[1]), "r"(a[2]), "r"(a[3]), "r"(b0), "r"(b1));
}
__device__ __forceinline__ void ldm_x4(uint32_t r[4], uint32_t addr) {
    asm volatile("ldmatrix.sync.aligned.m8n8.x4.shared.b16 {%0,%1,%2,%3}, [%4];"
        : "=r"(r[0]), "=r"(r[1]), "=r"(r[2]), "=r"(r[3]) : "r"(addr));
}

// ---------------------------------------------------------------------------
// tf32 mma.sync GEMM: C[M,N] = A[M,K] @ Bt[N,K]^T (+bias)
// A row-major [M,K], Bt row-major [N,K], both tf32-rounded fp32.
// M%128==0, N%128==0, K%16==0.  256 threads, 8 warps (2m x 4n), 64x32/warp.
// 5-stage cp.async pipeline (BK=16); fragments via ldmatrix.
// ---------------------------------------------------------------------------
__global__ __launch_bounds__(256, 2)
void gemm_tf32_kernel(const float* __restrict__ A, const float* __restrict__ Bt,
                      float* __restrict__ C, const float* __restrict__ bias,
                      int M, int N, int K)
{
    extern __shared__ float smem[];
    const uint32_t sbase = smem_u32(smem);

    const int tid  = threadIdx.x;
    const int wid  = tid >> 5;
    const int lane = tid & 31;
    const int wm = (wid & 1) * 64;     // warp m offset
    const int wn = (wid >> 1) * 32;    // warp n offset
    const int qr = lane >> 2;          // 0..7
    const int qc = lane & 3;           // 0..3

    const int nbase = blockIdx.x * BN;
    const size_t mbase = (size_t)blockIdx.y * BM;

    const int row_ld = tid >> 1;            // 0..127
    const int c2_ld  = (tid & 1) << 1;      // 16B-chunk 0 or 2 (of 4)

    // ldmatrix per-lane offsets within a stage buffer
    const int r8  = lane & 7;
    const int sel = lane >> 3;
    uint32_t a_off[4], b_off[2];
    #pragma unroll
    for (int i = 0; i < 4; i++)
        a_off[i] = (uint32_t)((wm + 16 * i + ((sel & 1) << 3) + r8) * SROW) * 4u
                 + ((uint32_t)(sel >> 1) << 4);
    #pragma unroll
    for (int p = 0; p < 2; p++)
        b_off[p] = (uint32_t)ABUF
                 + (uint32_t)((wn + 16 * p + ((sel >> 1) << 3) + r8) * SROW) * 4u
                 + ((uint32_t)(sel & 1) << 4);

    float acc[4][4][4];
    #pragma unroll
    for (int i = 0; i < 4; i++)
        #pragma unroll
        for (int j = 0; j < 4; j++)
            #pragma unroll
            for (int t = 0; t < 4; t++) acc[i][j][t] = 0.f;

    const int nstages = K / BK;

    auto load_stage = [&](int s) {
        const uint32_t base = sbase + (uint32_t)(s % NSTAGE) * STAGE_BYTES;
        const int k0 = s * BK;
        const float* Ag = A + (mbase + row_ld) * (size_t)K + k0;
        const float* Bg = Bt + (size_t)(nbase + row_ld) * K + k0;
        const uint32_t soff = (uint32_t)row_ld * (SROW * 4);
        #pragma unroll
        for (int cc = 0; cc < 2; cc++) {
            cp_async16(base + soff + ((c2_ld + cc) << 4), Ag + ((c2_ld + cc) << 2));
            cp_async16(base + ABUF + soff + ((c2_ld + cc) << 4), Bg + ((c2_ld + cc) << 2));
        }
        asm volatile("cp.async.commit_group;");
    };

    load_stage(0);
    load_stage(1);
    load_stage(2);
    load_stage(3);

    for (int s = 0; s < nstages; s++) {
        // wait until stage s has landed (tail-exact)
        if      (s + 3 < nstages) cp_wait<3>();
        else if (s + 2 < nstages) cp_wait<2>();
        else if (s + 1 < nstages) cp_wait<1>();
        else                      cp_wait<0>();
        __syncthreads();
        if (s + 4 < nstages) load_stage(s + 4);

        const uint32_t sstage = sbase + (uint32_t)(s % NSTAGE) * STAGE_BYTES;
        #pragma unroll
        for (int ks = 0; ks < 2; ks++) {
            const uint32_t kb = (uint32_t)ks << 5;   // ks * 32 bytes
            uint32_t afr[4][4];
            uint32_t bfr[2][4];
            #pragma unroll
            for (int i = 0; i < 4; i++) ldm_x4(afr[i], sstage + a_off[i] + kb);
            #pragma unroll
            for (int p = 0; p < 2; p++) ldm_x4(bfr[p], sstage + b_off[p] + kb);
            #pragma unroll
            for (int i = 0; i < 4; i++)
                #pragma unroll
                for (int j = 0; j < 4; j++)
                    mma_tf32(acc[i][j], afr[i], bfr[j >> 1][(j & 1) * 2],
                             bfr[j >> 1][(j & 1) * 2 + 1]);
        }
    }

    // Epilogue
    #pragma unroll
    for (int i = 0; i < 4; i++) {
        float* Crow0 = C + (mbase + wm + i * 16 + qr) * (size_t)N + nbase + wn;
        float* Crow1 = Crow0 + 8 * (size_t)N;
        #pragma unroll
        for (int j = 0; j < 4; j++) {
            const int col = j * 8 + 2 * qc;
            float2 v0 = make_float2(acc[i][j][0], acc[i][j][1]);
            float2 v1 = make_float2(acc[i][j][2], acc[i][j][3]);
            if (bias) {
                float2 bb = *(const float2*)(bias + nbase + wn + col);
                v0.x += bb.x; v0.y += bb.y;
                v1.x += bb.x; v1.y += bb.y;
            }
            *(float2*)(Crow0 + col) = v0;
            *(float2*)(Crow1 + col) = v1;
        }
    }
}

// ---------------------------------------------------------------------------
__global__ void round_tf32_kernel(const float* __restrict__ in, float* __restrict__ out, int n4)
{
    int i = blockIdx.x * blockDim.x + threadIdx.x;
    if (i >= n4) return;
    float4 v = ((const float4*)in)[i];
    v.x = round_tf32(v.x); v.y = round_tf32(v.y);
    v.z = round_tf32(v.z); v.w = round_tf32(v.w);
    ((float4*)out)[i] = v;
}

// Transpose + tf32 round: out[n*K + k] = rna(in[k*N + n]).  in: [K][N]
__global__ void transpose_round_kernel(const float* __restrict__ in, float* __restrict__ out,
                                       int K, int N)
{
    int i = blockIdx.x * blockDim.x + threadIdx.x;
    if (i >= K * N) return;
    int n = i % N, k = i / N;
    out[(size_t)n * K + k] = round_tf32(in[(size_t)k * N + n]);
}

// ---------------------------------------------------------------------------
// Windowed attention: one block per (batch, window, head), 64 threads,
// one thread per q-row. k/v in smem (broadcast reads), S in padded smem.
// ---------------------------------------------------------------------------
__global__ __launch_bounds__(64) void attn_kernel(
    const float* __restrict__ qkv, float* __restrict__ y)
{
    __shared__ float ks[WIN][HD];
    __shared__ float vs[WIN][HD];
    __shared__ float S[64][53];

    const int tid = threadIdx.x;
    int bwh = blockIdx.x;
    const int h = bwh % NHEADS; bwh /= NHEADS;
    const int w = bwh & 63; const int b = bwh >> 6;
    const int hi = w >> 3, wi = w & 7;
    const int col0 = h * HD;

    for (int t = tid; t < WIN * 8; t += 64) {
        int row = t >> 3, c4 = (t & 7) << 2;
        int n = (hi * 7 + row / 7) * 56 + wi * 7 + (row % 7);
        const float* p = qkv + ((size_t)(b * NN + n)) * C3 + col0 + c4;
        *(float4*)&ks[row][c4] = *(const float4*)(p + CC);
        *(float4*)&vs[row][c4] = *(const float4*)(p + 2 * CC);
    }

    const int i = tid;
    const bool active = (i < WIN);
    int n_i = 0;
    float q[HD];
    if (active) {
        n_i = (hi * 7 + i / 7) * 56 + wi * 7 + (i % 7);
        const float* p = qkv + ((size_t)(b * NN + n_i)) * C3 + col0;
        #pragma unroll
        for (int c4 = 0; c4 < 8; c4++) {
            float4 v = *(const float4*)(p + c4 * 4);
            q[c4 * 4 + 0] = v.x; q[c4 * 4 + 1] = v.y;
            q[c4 * 4 + 2] = v.z; q[c4 * 4 + 3] = v.w;
        }
    }
    __syncthreads();

    if (active) {
        const float scale = 0.17677669529663687f;  // 32^-0.5
        float m = -1e30f;
        #pragma unroll 4
        for (int j = 0; j < WIN; j++) {
            float acc = 0.f;
            #pragma unroll
            for (int c4 = 0; c4 < 8; c4++) {
                float4 kv = *(const float4*)&ks[j][c4 * 4];
                acc += q[c4 * 4 + 0] * kv.x + q[c4 * 4 + 1] * kv.y +
                       q[c4 * 4 + 2] * kv.z + q[c4 * 4 + 3] * kv.w;
            }
            acc *= scale;
            S[i][j] = acc;
            m = fmaxf(m, acc);
        }
        float sum = 0.f;
        #pragma unroll 4
        for (int j = 0; j < WIN; j++) {
            float e = __expf(S[i][j] - m);
            sum += e;
            S[i][j] = e;
        }
        const float inv = 1.f / sum;

        float o[HD];
        #pragma unroll
        for (int d = 0; d < HD; d++) o[d] = 0.f;
        #pragma unroll 4
        for (int j = 0; j < WIN; j++) {
            float pj = S[i][j] * inv;
            #pragma unroll
            for (int c4 = 0; c4 < 8; c4++) {
                float4 vv = *(const float4*)&vs[j][c4 * 4];
                o[c4 * 4 + 0] += pj * vv.x; o[c4 * 4 + 1] += pj * vv.y;
                o[c4 * 4 + 2] += pj * vv.z; o[c4 * 4 + 3] += pj * vv.w;
            }
        }
        float* yo = y + ((size_t)(b * NN + n_i)) * CC + col0;
        #pragma unroll
        for (int c4 = 0; c4 < 8; c4++) {
            float4 r;
            r.x = o[c4 * 4 + 0]; r.y = o[c4 * 4 + 1];
            r.z = o[c4 * 4 + 2]; r.w = o[c4 * 4 + 3];
            *(float4*)(yo + c4 * 4) = r;
        }
    }
}

// ---------------------------------------------------------------------------
// Depthwise 3x3 conv (SAME) on v + residual add into y, float4 per thread.
// ---------------------------------------------------------------------------
__global__ void conv_add_kernel(
    const float* __restrict__ qkv,
    const float* __restrict__ w_conv,
    const float* __restrict__ b_conv,
    float* __restrict__ y)
{
    const int C4 = CC / 4;
    int idx = blockIdx.x * blockDim.x + threadIdx.x;
    if (idx >= BATCH * NN * C4) return;
    int c4 = idx % C4;
    int n = (idx / C4) % NN;
    int b = idx / (C4 * NN);
    int hh = n / WW, ww = n % WW;
    const int c = c4 * 4;

    float4 acc = *(const float4*)(b_conv + c);
    #pragma unroll
    for (int kh = 0; kh < 3; kh++) {
        int hn = hh + kh - 1;
        if ((unsigned)hn >= (unsigned)HH) continue;
        #pragma unroll
        for (int kw = 0; kw < 3; kw++) {
            int wn = ww + kw - 1;
            if ((unsigned)wn >= (unsigned)WW) continue;
            float4 v = *(const float4*)(qkv + ((size_t)(b * NN + hn * WW + wn)) * C3 + 2 * CC + c);
            float4 wv = *(const float4*)(w_conv + (kh * 3 + kw) * CC + c);
            acc.x += v.x * wv.x; acc.y += v.y * wv.y;
            acc.z += v.z * wv.z; acc.w += v.w * wv.w;
        }
    }
    float4 yv = *(float4*)(y + (size_t)idx * 4);
    yv.x = round_tf32(yv.x + acc.x);
    yv.y = round_tf32(yv.y + acc.y);
    yv.z = round_tf32(yv.z + acc.z);
    yv.w = round_tf32(yv.w + acc.w);
    *(float4*)(y + (size_t)idx * 4) = yv;
}

// ---------------------------------------------------------------------------
extern "C" void kernel_launch(void* const* d_in, const int* in_sizes, int n_in,
                              void* d_out, int out_size)
{
    const float* x      = (const float*)d_in[0];
    const float* w_qkv  = (const float*)d_in[1];
    const float* w_proj = (const float*)d_in[2];
    const float* b_proj = (const float*)d_in[3];
    const float* w_conv = (const float*)d_in[4];
    const float* b_conv = (const float*)d_in[5];
    float* out = (float*)d_out;

    float *qkv_p, *y_p, *xr_p, *wt1_p, *wt2_p;
    cudaGetSymbolAddress((void**)&qkv_p, g_qkv);
    cudaGetSymbolAddress((void**)&y_p, g_y);
    cudaGetSymbolAddress((void**)&xr_p, g_xr);
    cudaGetSymbolAddress((void**)&wt1_p, g_wt1);
    cudaGetSymbolAddress((void**)&wt2_p, g_wt2);

    const int gemm_smem = NSTAGE * STAGE_BYTES;  // 102400
    cudaFuncSetAttribute(gemm_tf32_kernel,
                         cudaFuncAttributeMaxDynamicSharedMemorySize, gemm_smem);

    // 0) tf32-RNA rounding of x + transposed/rounded weights
    {
        int n4 = MROWS * CC / 4;
        round_tf32_kernel<<<(n4 + 255) / 256, 256>>>(x, xr_p, n4);
        transpose_round_kernel<<<(CC * C3 + 255) / 256, 256>>>(w_qkv, wt1_p, CC, C3);
        transpose_round_kernel<<<(CC * CC + 255) / 256, 256>>>(w_proj, wt2_p, CC, CC);
    }
    // 1) qkv = x @ w_qkv   (50176 x 1152 x 384) via mma.sync tf32
    {
        dim3 grid(C3 / BN, MROWS / BM);
        gemm_tf32_kernel<<<grid, 256, gemm_smem>>>(xr_p, wt1_p, qkv_p, nullptr,
                                                   MROWS, C3, CC);
    }
    // 2) windowed attention -> y
    attn_kernel<<<BATCH * 64 * NHEADS, 64>>>(qkv_p, y_p);
    // 3) y = round_tf32(y + depthwise_conv3x3(v) + b_conv)
    {
        int total = BATCH * NN * (CC / 4);
        conv_add_kernel<<<(total + 255) / 256, 256>>>(qkv_p, w_conv, b_conv, y_p);
    }
    // 4) out = y @ w_proj + b_proj   (50176 x 384 x 384) via mma.sync tf32
    {
        dim3 grid(CC / BN, MROWS / BM);
        gemm_tf32_kernel<<<grid, 256, gemm_smem>>>(y_p, wt2_p, out, b_proj,
                                                   MROWS, CC, CC);
    }
}

// round 6
// speedup vs baseline: 1.9803x; 1.9803x over previous
#include <cuda_runtime.h>
#include <cuda_fp16.h>
#include <cstdint>

// Problem constants
#define BATCH 16
#define HH 56
#define WW 56
#define NN (HH * WW)          // 3136
#define CC 384
#define C3 (3 * CC)           // 1152
#define NHEADS 12
#define HD 32
#define WSZ 7
#define WIN 49
#define MROWS (BATCH * NN)    // 50176

// GEMM tiling (fp16 path)
#define BM 128
#define BN 128
#define BK 32                     // halves per stage along K
#define SROWH 40                  // smem row stride in halves (80B, ldmatrix conflict-free)
#define ABUF (BM * SROWH * 2)     // 10240 bytes per A (or B) buffer
#define STAGE_BYTES (2 * ABUF)    // 20480
#define NSTAGE 4

// Scratch (allocation-free rule: __device__ globals)
__device__ float  g_qkv[(size_t)MROWS * C3];    // 231 MB (fp32 for attention)
__device__ float  g_y[(size_t)MROWS * CC];      // 77 MB  (attention out, fp32)
__device__ __half g_xh[(size_t)MROWS * CC];     // 38.5 MB (fp16 x)
__device__ __half g_yh[(size_t)MROWS * CC];     // 38.5 MB (fp16 y+conv)
__device__ __half g_wt1[(size_t)C3 * CC];       // w_qkv^T [1152][384] fp16
__device__ __half g_wt2[(size_t)CC * CC];       // w_proj^T [384][384] fp16

// ---------------------------------------------------------------------------
__device__ __forceinline__ uint32_t smem_u32(const void* p) {
    uint32_t a;
    asm("{ .reg .u64 t; cvta.to.shared.u64 t, %1; cvt.u32.u64 %0, t; }" : "=r"(a) : "l"(p));
    return a;
}
__device__ __forceinline__ void cp_async16(uint32_t saddr, const void* gaddr) {
    asm volatile("cp.async.cg.shared.global [%0], [%1], 16;" :: "r"(saddr), "l"(gaddr));
}
template <int N>
__device__ __forceinline__ void cp_wait() {
    asm volatile("cp.async.wait_group %0;" :: "n"(N) : "memory");
}
__device__ __forceinline__ void mma_f16(float c[4], const uint32_t a[4],
                                        uint32_t b0, uint32_t b1) {
    asm volatile(
        "mma.sync.aligned.m16n8k16.row.col.f32.f16.f16.f32 "
        "{%0,%1,%2,%3}, {%4,%5,%6,%7}, {%8,%9}, {%0,%1,%2,%3};"
        : "+f"(c[0]), "+f"(c[1]), "+f"(c[2]), "+f"(c[3])
        : "r"(a[0]), "r"(a[1]), "r"(a[2]), "r"(a[3]), "r"(b0), "r"(b1));
}
__device__ __forceinline__ void ldm_x4(uint32_t r[4], uint32_t addr) {
    asm volatile("ldmatrix.sync.aligned.m8n8.x4.shared.b16 {%0,%1,%2,%3}, [%4];"
        : "=r"(r[0]), "=r"(r[1]), "=r"(r[2]), "=r"(r[3]) : "r"(addr));
}

// ---------------------------------------------------------------------------
// fp16 mma.sync GEMM: C[M,N](fp32) = A[M,K] @ Bt[N,K]^T (+bias)
// A row-major [M,K] half, Bt row-major [N,K] half. M%128==0, N%128==0, K%32==0.
// 256 threads, 8 warps (2m x 4n), 64x32 per warp. 4-stage cp.async, BK=32.
// ---------------------------------------------------------------------------
__global__ __launch_bounds__(256, 2)
void gemm_f16_kernel(const __half* __restrict__ A, const __half* __restrict__ Bt,
                     float* __restrict__ C, const float* __restrict__ bias,
                     int M, int N, int K)
{
    extern __shared__ char smem[];
    const uint32_t sbase = smem_u32(smem);

    const int tid  = threadIdx.x;
    const int wid  = tid >> 5;
    const int lane = tid & 31;
    const int wm = (wid & 1) * 64;
    const int wn = (wid >> 1) * 32;
    const int qr = lane >> 2;
    const int qc = lane & 3;

    const int nbase = blockIdx.x * BN;
    const size_t mbase = (size_t)blockIdx.y * BM;

    const int row_ld = tid >> 1;           // 0..127 (2 threads/row)
    const int c2_ld  = (tid & 1) << 1;     // 16B chunk 0 or 2 (of 4 per 64B row)

    // ldmatrix per-lane offsets within a stage buffer.
    // lanes 0-7: rows+0 @k0 | 8-15: rows+8 @k0 | 16-23: rows+0 @k+16B | 24-31: rows+8 @k+16B
    const int r8  = lane & 7;
    const int sel = lane >> 3;
    const uint32_t rowadd = (uint32_t)((sel & 1) << 3);
    const uint32_t kbadd  = (uint32_t)((sel >> 1) << 4);
    uint32_t a_off[4], b_off[2];
    #pragma unroll
    for (int i = 0; i < 4; i++)
        a_off[i] = (uint32_t)(wm + 16 * i + rowadd + r8) * (SROWH * 2) + kbadd;
    #pragma unroll
    for (int p = 0; p < 2; p++)
        b_off[p] = (uint32_t)ABUF
                 + (uint32_t)(wn + 16 * p + rowadd + r8) * (SROWH * 2) + kbadd;

    float acc[4][4][4];
    #pragma unroll
    for (int i = 0; i < 4; i++)
        #pragma unroll
        for (int j = 0; j < 4; j++)
            #pragma unroll
            for (int t = 0; t < 4; t++) acc[i][j][t] = 0.f;

    const int nstages = K / BK;

    auto load_stage = [&](int s) {
        const uint32_t base = sbase + (uint32_t)(s % NSTAGE) * STAGE_BYTES;
        const int k0 = s * BK;
        const __half* Ag = A + (mbase + row_ld) * (size_t)K + k0;
        const __half* Bg = Bt + (size_t)(nbase + row_ld) * K + k0;
        const uint32_t soff = (uint32_t)row_ld * (SROWH * 2);
        #pragma unroll
        for (int cc = 0; cc < 2; cc++) {
            const int ch = c2_ld + cc;                 // 16B chunk = 8 halves
            cp_async16(base + soff + ((uint32_t)ch << 4), Ag + (ch << 3));
            cp_async16(base + ABUF + soff + ((uint32_t)ch << 4), Bg + (ch << 3));
        }
        asm volatile("cp.async.commit_group;");
    };

    load_stage(0);
    load_stage(1);
    load_stage(2);

    for (int s = 0; s < nstages; s++) {
        if      (s + 2 < nstages) cp_wait<2>();
        else if (s + 1 < nstages) cp_wait<1>();
        else                      cp_wait<0>();
        __syncthreads();
        if (s + 3 < nstages) load_stage(s + 3);

        const uint32_t sstage = sbase + (uint32_t)(s % NSTAGE) * STAGE_BYTES;
        #pragma unroll
        for (int ks = 0; ks < 2; ks++) {               // 2 k-steps of K=16
            const uint32_t kb = (uint32_t)ks << 5;     // 16 halves = 32 bytes
            uint32_t afr[4][4];
            uint32_t bfr[2][4];
            #pragma unroll
            for (int i = 0; i < 4; i++) ldm_x4(afr[i], sstage + a_off[i] + kb);
            #pragma unroll
            for (int p = 0; p < 2; p++) ldm_x4(bfr[p], sstage + b_off[p] + kb);
            // n8-tile j: pair p=j>>1, q=j&1: b0=bfr[p][q], b1=bfr[p][q+2]
            #pragma unroll
            for (int i = 0; i < 4; i++)
                #pragma unroll
                for (int j = 0; j < 4; j++)
                    mma_f16(acc[i][j], afr[i], bfr[j >> 1][j & 1],
                            bfr[j >> 1][(j & 1) + 2]);
        }
    }

    // Epilogue (m16n8 layout: c0,c1 -> row qr cols 2qc,2qc+1; c2,c3 -> row qr+8)
    #pragma unroll
    for (int i = 0; i < 4; i++) {
        float* Crow0 = C + (mbase + wm + i * 16 + qr) * (size_t)N + nbase + wn;
        float* Crow1 = Crow0 + 8 * (size_t)N;
        #pragma unroll
        for (int j = 0; j < 4; j++) {
            const int col = j * 8 + 2 * qc;
            float2 v0 = make_float2(acc[i][j][0], acc[i][j][1]);
            float2 v1 = make_float2(acc[i][j][2], acc[i][j][3]);
            if (bias) {
                float2 bb = *(const float2*)(bias + nbase + wn + col);
                v0.x += bb.x; v0.y += bb.y;
                v1.x += bb.x; v1.y += bb.y;
            }
            *(float2*)(Crow0 + col) = v0;
            *(float2*)(Crow1 + col) = v1;
        }
    }
}

// ---------------------------------------------------------------------------
// fp32 -> fp16 (vectorized: 4 floats -> 4 halves per thread)
__global__ void to_half_kernel(const float* __restrict__ in, __half* __restrict__ out, int n4)
{
    int i = blockIdx.x * blockDim.x + threadIdx.x;
    if (i >= n4) return;
    float4 v = ((const float4*)in)[i];
    __half2 h0 = __floats2half2_rn(v.x, v.y);
    __half2 h1 = __floats2half2_rn(v.z, v.w);
    ((__half2*)out)[i * 2 + 0] = h0;
    ((__half2*)out)[i * 2 + 1] = h1;
}

// Transpose + fp16: out[n*K + k] = (half)in[k*N + n].  in: [K][N]
__global__ void transpose_half_kernel(const float* __restrict__ in, __half* __restrict__ out,
                                      int K, int N)
{
    int i = blockIdx.x * blockDim.x + threadIdx.x;
    if (i >= K * N) return;
    int n = i % N, k = i / N;
    out[(size_t)n * K + k] = __float2half_rn(in[(size_t)k * N + n]);
}

// ---------------------------------------------------------------------------
// Windowed attention: one block per (batch, window, head), 64 threads,
// one thread per q-row. k/v in smem (broadcast reads), S in padded smem.
// ---------------------------------------------------------------------------
__global__ __launch_bounds__(64) void attn_kernel(
    const float* __restrict__ qkv, float* __restrict__ y)
{
    __shared__ float ks[WIN][HD];
    __shared__ float vs[WIN][HD];
    __shared__ float S[64][53];

    const int tid = threadIdx.x;
    int bwh = blockIdx.x;
    const int h = bwh % NHEADS; bwh /= NHEADS;
    const int w = bwh & 63; const int b = bwh >> 6;
    const int hi = w >> 3, wi = w & 7;
    const int col0 = h * HD;

    for (int t = tid; t < WIN * 8; t += 64) {
        int row = t >> 3, c4 = (t & 7) << 2;
        int n = (hi * 7 + row / 7) * 56 + wi * 7 + (row % 7);
        const float* p = qkv + ((size_t)(b * NN + n)) * C3 + col0 + c4;
        *(float4*)&ks[row][c4] = *(const float4*)(p + CC);
        *(float4*)&vs[row][c4] = *(const float4*)(p + 2 * CC);
    }

    const int i = tid;
    const bool active = (i < WIN);
    int n_i = 0;
    float q[HD];
    if (active) {
        n_i = (hi * 7 + i / 7) * 56 + wi * 7 + (i % 7);
        const float* p = qkv + ((size_t)(b * NN + n_i)) * C3 + col0;
        #pragma unroll
        for (int c4 = 0; c4 < 8; c4++) {
            float4 v = *(const float4*)(p + c4 * 4);
            q[c4 * 4 + 0] = v.x; q[c4 * 4 + 1] = v.y;
            q[c4 * 4 + 2] = v.z; q[c4 * 4 + 3] = v.w;
        }
    }
    __syncthreads();

    if (active) {
        const float scale = 0.17677669529663687f;  // 32^-0.5
        float m = -1e30f;
        #pragma unroll 4
        for (int j = 0; j < WIN; j++) {
            float acc = 0.f;
            #pragma unroll
            for (int c4 = 0; c4 < 8; c4++) {
                float4 kv = *(const float4*)&ks[j][c4 * 4];
                acc += q[c4 * 4 + 0] * kv.x + q[c4 * 4 + 1] * kv.y +
                       q[c4 * 4 + 2] * kv.z + q[c4 * 4 + 3] * kv.w;
            }
            acc *= scale;
            S[i][j] = acc;
            m = fmaxf(m, acc);
        }
        float sum = 0.f;
        #pragma unroll 4
        for (int j = 0; j < WIN; j++) {
            float e = __expf(S[i][j] - m);
            sum += e;
            S[i][j] = e;
        }
        const float inv = 1.f / sum;

        float o[HD];
        #pragma unroll
        for (int d = 0; d < HD; d++) o[d] = 0.f;
        #pragma unroll 4
        for (int j = 0; j < WIN; j++) {
            float pj = S[i][j] * inv;
            #pragma unroll
            for (int c4 = 0; c4 < 8; c4++) {
                float4 vv = *(const float4*)&vs[j][c4 * 4];
                o[c4 * 4 + 0] += pj * vv.x; o[c4 * 4 + 1] += pj * vv.y;
                o[c4 * 4 + 2] += pj * vv.z; o[c4 * 4 + 3] += pj * vv.w;
            }
        }
        float* yo = y + ((size_t)(b * NN + n_i)) * CC + col0;
        #pragma unroll
        for (int c4 = 0; c4 < 8; c4++) {
            float4 r;
            r.x = o[c4 * 4 + 0]; r.y = o[c4 * 4 + 1];
            r.z = o[c4 * 4 + 2]; r.w = o[c4 * 4 + 3];
            *(float4*)(yo + c4 * 4) = r;
        }
    }
}

// ---------------------------------------------------------------------------
// Depthwise 3x3 conv (SAME) on v + residual add; writes fp16 for second GEMM.
// ---------------------------------------------------------------------------
__global__ void conv_add_kernel(
    const float* __restrict__ qkv,
    const float* __restrict__ w_conv,
    const float* __restrict__ b_conv,
    const float* __restrict__ y,
    __half* __restrict__ yh)
{
    const int C4 = CC / 4;
    int idx = blockIdx.x * blockDim.x + threadIdx.x;
    if (idx >= BATCH * NN * C4) return;
    int c4 = idx % C4;
    int n = (idx / C4) % NN;
    int b = idx / (C4 * NN);
    int hh = n / WW, ww = n % WW;
    const int c = c4 * 4;

    float4 acc = *(const float4*)(b_conv + c);
    #pragma unroll
    for (int kh = 0; kh < 3; kh++) {
        int hn = hh + kh - 1;
        if ((unsigned)hn >= (unsigned)HH) continue;
        #pragma unroll
        for (int kw = 0; kw < 3; kw++) {
            int wn = ww + kw - 1;
            if ((unsigned)wn >= (unsigned)WW) continue;
            float4 v = *(const float4*)(qkv + ((size_t)(b * NN + hn * WW + wn)) * C3 + 2 * CC + c);
            float4 wv = *(const float4*)(w_conv + (kh * 3 + kw) * CC + c);
            acc.x += v.x * wv.x; acc.y += v.y * wv.y;
            acc.z += v.z * wv.z; acc.w += v.w * wv.w;
        }
    }
    float4 yv = *(const float4*)(y + (size_t)idx * 4);
    __half2 h0 = __floats2half2_rn(yv.x + acc.x, yv.y + acc.y);
    __half2 h1 = __floats2half2_rn(yv.z + acc.z, yv.w + acc.w);
    ((__half2*)yh)[idx * 2 + 0] = h0;
    ((__half2*)yh)[idx * 2 + 1] = h1;
}

// ---------------------------------------------------------------------------
extern "C" void kernel_launch(void* const* d_in, const int* in_sizes, int n_in,
                              void* d_out, int out_size)
{
    const float* x      = (const float*)d_in[0];
    const float* w_qkv  = (const float*)d_in[1];
    const float* w_proj = (const float*)d_in[2];
    const float* b_proj = (const float*)d_in[3];
    const float* w_conv = (const float*)d_in[4];
    const float* b_conv = (const float*)d_in[5];
    float* out = (float*)d_out;

    float *qkv_p, *y_p;
    __half *xh_p, *yh_p, *wt1_p, *wt2_p;
    cudaGetSymbolAddress((void**)&qkv_p, g_qkv);
    cudaGetSymbolAddress((void**)&y_p, g_y);
    cudaGetSymbolAddress((void**)&xh_p, g_xh);
    cudaGetSymbolAddress((void**)&yh_p, g_yh);
    cudaGetSymbolAddress((void**)&wt1_p, g_wt1);
    cudaGetSymbolAddress((void**)&wt2_p, g_wt2);

    const int gemm_smem = NSTAGE * STAGE_BYTES;  // 81920
    cudaFuncSetAttribute(gemm_f16_kernel,
                         cudaFuncAttributeMaxDynamicSharedMemorySize, gemm_smem);

    // 0) fp16 conversions: x and transposed weights
    {
        int n4 = MROWS * CC / 4;
        to_half_kernel<<<(n4 + 255) / 256, 256>>>(x, xh_p, n4);
        transpose_half_kernel<<<(CC * C3 + 255) / 256, 256>>>(w_qkv, wt1_p, CC, C3);
        transpose_half_kernel<<<(CC * CC + 255) / 256, 256>>>(w_proj, wt2_p, CC, CC);
    }
    // 1) qkv = x @ w_qkv   (50176 x 1152 x 384) fp16 mma.sync
    {
        dim3 grid(C3 / BN, MROWS / BM);
        gemm_f16_kernel<<<grid, 256, gemm_smem>>>(xh_p, wt1_p, qkv_p, nullptr,
                                                  MROWS, C3, CC);
    }
    // 2) windowed attention -> y (fp32)
    attn_kernel<<<BATCH * 64 * NHEADS, 64>>>(qkv_p, y_p);
    // 3) yh = (half)(y + depthwise_conv3x3(v) + b_conv)
    {
        int total = BATCH * NN * (CC / 4);
        conv_add_kernel<<<(total + 255) / 256, 256>>>(qkv_p, w_conv, b_conv, y_p, yh_p);
    }
    // 4) out = y @ w_proj + b_proj   (50176 x 384 x 384) fp16 mma.sync
    {
        dim3 grid(CC / BN, MROWS / BM);
        gemm_f16_kernel<<<grid, 256, gemm_smem>>>(yh_p, wt2_p, out, b_proj,
                                                  MROWS, CC, CC);
    }
}

// round 7
// speedup vs baseline: 1.9953x; 1.0076x over previous
#include <cuda_runtime.h>
#include <cuda_fp16.h>
#include <cstdint>

// Problem constants
#define BATCH 16
#define HH 56
#define WW 56
#define NN (HH * WW)          // 3136
#define CC 384
#define C3 (3 * CC)           // 1152
#define NHEADS 12
#define HD 32
#define WSZ 7
#define WIN 49
#define MROWS (BATCH * NN)    // 50176

// GEMM tiling (fp16 path)
#define BM 128
#define BN 128
#define BK 32
#define SROWH 40                  // smem row stride in halves (80B, conflict-free)
#define ABUF (BM * SROWH * 2)     // 10240 bytes per buffer
#define STAGE_BYTES (2 * ABUF)    // 20480
#define NSTAGE 4

// Scratch (allocation-free rule: __device__ globals)
__device__ __half g_qkvh[(size_t)MROWS * C3];   // 115.5 MB (fp16 qkv)
__device__ __half g_xh[(size_t)MROWS * CC];     // 38.5 MB (fp16 x)
__device__ __half g_yh[(size_t)MROWS * CC];     // 38.5 MB (fp16 attn+conv out)
__device__ __half g_wt1[(size_t)C3 * CC];       // w_qkv^T [1152][384] fp16
__device__ __half g_wt2[(size_t)CC * CC];       // w_proj^T [384][384] fp16

// ---------------------------------------------------------------------------
__device__ __forceinline__ uint32_t smem_u32(const void* p) {
    uint32_t a;
    asm("{ .reg .u64 t; cvta.to.shared.u64 t, %1; cvt.u32.u64 %0, t; }" : "=r"(a) : "l"(p));
    return a;
}
__device__ __forceinline__ void cp_async16(uint32_t saddr, const void* gaddr) {
    asm volatile("cp.async.cg.shared.global [%0], [%1], 16;" :: "r"(saddr), "l"(gaddr));
}
template <int N>
__device__ __forceinline__ void cp_wait() {
    asm volatile("cp.async.wait_group %0;" :: "n"(N) : "memory");
}
__device__ __forceinline__ void mma_f16(float c[4], const uint32_t a[4],
                                        uint32_t b0, uint32_t b1) {
    asm volatile(
        "mma.sync.aligned.m16n8k16.row.col.f32.f16.f16.f32 "
        "{%0,%1,%2,%3}, {%4,%5,%6,%7}, {%8,%9}, {%0,%1,%2,%3};"
        : "+f"(c[0]), "+f"(c[1]), "+f"(c[2]), "+f"(c[3])
        : "r"(a[0]), "r"(a[1]), "r"(a[2]), "r"(a[3]), "r"(b0), "r"(b1));
}
__device__ __forceinline__ void ldm_x4(uint32_t r[4], uint32_t addr) {
    asm volatile("ldmatrix.sync.aligned.m8n8.x4.shared.b16 {%0,%1,%2,%3}, [%4];"
        : "=r"(r[0]), "=r"(r[1]), "=r"(r[2]), "=r"(r[3]) : "r"(addr));
}

// ---------------------------------------------------------------------------
// fp16 mma.sync GEMM: C[M,N] = A[M,K] @ Bt[N,K]^T (+bias for fp32 out).
// HALF_OUT=true writes __half C, else fp32. 256 thr, 8 warps (2m x 4n),
// 64x32/warp, 4-stage cp.async BK=32, ldmatrix fragments.
// ---------------------------------------------------------------------------
template <bool HALF_OUT>
__global__ __launch_bounds__(256, 2)
void gemm_f16_kernel(const __half* __restrict__ A, const __half* __restrict__ Bt,
                     void* __restrict__ Cout, const float* __restrict__ bias,
                     int M, int N, int K)
{
    extern __shared__ char smem[];
    const uint32_t sbase = smem_u32(smem);

    const int tid  = threadIdx.x;
    const int wid  = tid >> 5;
    const int lane = tid & 31;
    const int wm = (wid & 1) * 64;
    const int wn = (wid >> 1) * 32;
    const int qr = lane >> 2;
    const int qc = lane & 3;

    const int nbase = blockIdx.x * BN;
    const size_t mbase = (size_t)blockIdx.y * BM;

    const int row_ld = tid >> 1;
    const int c2_ld  = (tid & 1) << 1;

    const int r8  = lane & 7;
    const int sel = lane >> 3;
    const uint32_t rowadd = (uint32_t)((sel & 1) << 3);
    const uint32_t kbadd  = (uint32_t)((sel >> 1) << 4);
    uint32_t a_off[4], b_off[2];
    #pragma unroll
    for (int i = 0; i < 4; i++)
        a_off[i] = (uint32_t)(wm + 16 * i + rowadd + r8) * (SROWH * 2) + kbadd;
    #pragma unroll
    for (int p = 0; p < 2; p++)
        b_off[p] = (uint32_t)ABUF
                 + (uint32_t)(wn + 16 * p + rowadd + r8) * (SROWH * 2) + kbadd;

    float acc[4][4][4];
    #pragma unroll
    for (int i = 0; i < 4; i++)
        #pragma unroll
        for (int j = 0; j < 4; j++)
            #pragma unroll
            for (int t = 0; t < 4; t++) acc[i][j][t] = 0.f;

    const int nstages = K / BK;

    auto load_stage = [&](int s) {
        const uint32_t base = sbase + (uint32_t)(s % NSTAGE) * STAGE_BYTES;
        const int k0 = s * BK;
        const __half* Ag = A + (mbase + row_ld) * (size_t)K + k0;
        const __half* Bg = Bt + (size_t)(nbase + row_ld) * K + k0;
        const uint32_t soff = (uint32_t)row_ld * (SROWH * 2);
        #pragma unroll
        for (int cc = 0; cc < 2; cc++) {
            const int ch = c2_ld + cc;
            cp_async16(base + soff + ((uint32_t)ch << 4), Ag + (ch << 3));
            cp_async16(base + ABUF + soff + ((uint32_t)ch << 4), Bg + (ch << 3));
        }
        asm volatile("cp.async.commit_group;");
    };

    load_stage(0);
    load_stage(1);
    load_stage(2);

    for (int s = 0; s < nstages; s++) {
        if      (s + 2 < nstages) cp_wait<2>();
        else if (s + 1 < nstages) cp_wait<1>();
        else                      cp_wait<0>();
        __syncthreads();
        if (s + 3 < nstages) load_stage(s + 3);

        const uint32_t sstage = sbase + (uint32_t)(s % NSTAGE) * STAGE_BYTES;
        #pragma unroll
        for (int ks = 0; ks < 2; ks++) {
            const uint32_t kb = (uint32_t)ks << 5;
            uint32_t afr[4][4];
            uint32_t bfr[2][4];
            #pragma unroll
            for (int i = 0; i < 4; i++) ldm_x4(afr[i], sstage + a_off[i] + kb);
            #pragma unroll
            for (int p = 0; p < 2; p++) ldm_x4(bfr[p], sstage + b_off[p] + kb);
            #pragma unroll
            for (int i = 0; i < 4; i++)
                #pragma unroll
                for (int j = 0; j < 4; j++)
                    mma_f16(acc[i][j], afr[i], bfr[j >> 1][j & 1],
                            bfr[j >> 1][(j & 1) + 2]);
        }
    }

    // Epilogue
    #pragma unroll
    for (int i = 0; i < 4; i++) {
        const size_t row = mbase + wm + i * 16 + qr;
        #pragma unroll
        for (int j = 0; j < 4; j++) {
            const int col = nbase + wn + j * 8 + 2 * qc;
            if (HALF_OUT) {
                __half* Ch = (__half*)Cout;
                *(__half2*)(Ch + row * (size_t)N + col) =
                    __floats2half2_rn(acc[i][j][0], acc[i][j][1]);
                *(__half2*)(Ch + (row + 8) * (size_t)N + col) =
                    __floats2half2_rn(acc[i][j][2], acc[i][j][3]);
            } else {
                float* Cf = (float*)Cout;
                float2 v0 = make_float2(acc[i][j][0], acc[i][j][1]);
                float2 v1 = make_float2(acc[i][j][2], acc[i][j][3]);
                if (bias) {
                    float2 bb = *(const float2*)(bias + col);
                    v0.x += bb.x; v0.y += bb.y;
                    v1.x += bb.x; v1.y += bb.y;
                }
                *(float2*)(Cf + row * (size_t)N + col) = v0;
                *(float2*)(Cf + (row + 8) * (size_t)N + col) = v1;
            }
        }
    }
}

// ---------------------------------------------------------------------------
__global__ void to_half_kernel(const float* __restrict__ in, __half* __restrict__ out, int n4)
{
    int i = blockIdx.x * blockDim.x + threadIdx.x;
    if (i >= n4) return;
    float4 v = ((const float4*)in)[i];
    ((__half2*)out)[i * 2 + 0] = __floats2half2_rn(v.x, v.y);
    ((__half2*)out)[i * 2 + 1] = __floats2half2_rn(v.z, v.w);
}

__global__ void transpose_half_kernel(const float* __restrict__ in, __half* __restrict__ out,
                                      int K, int N)
{
    int i = blockIdx.x * blockDim.x + threadIdx.x;
    if (i >= K * N) return;
    int n = i % N, k = i / N;
    out[(size_t)n * K + k] = __float2half_rn(in[(size_t)k * N + n]);
}

// ---------------------------------------------------------------------------
// Fused windowed attention + depthwise 3x3 conv(v) + bias.
// One block per (batch, window, head), 64 threads, one thread per q-row.
// qkv is fp16; math fp32; output fp16 into yh.
// ---------------------------------------------------------------------------
__global__ __launch_bounds__(64) void attn_conv_kernel(
    const __half* __restrict__ qkvh,
    const float* __restrict__ w_conv,
    const float* __restrict__ b_conv,
    __half* __restrict__ yh)
{
    __shared__ float  ks[WIN][HD];
    __shared__ float  vs[WIN][HD];
    __shared__ float  S[WIN][53];
    __shared__ __half2 vh[81][17];     // 9x9 halo of v (fp16), padded stride
    __shared__ float  wcs[9][HD];
    __shared__ float  bcs[HD];

    const int tid = threadIdx.x;
    int bwh = blockIdx.x;
    const int h = bwh % NHEADS; bwh /= NHEADS;
    const int w = bwh & 63; const int b = bwh >> 6;
    const int hi = w >> 3, wi = w & 7;
    const int col0 = h * HD;
    const int row0 = hi * 7, cp0 = wi * 7;   // window origin in image

    // k, v tiles (convert fp16 -> fp32 smem). 49 rows x 4 chunks of 8 halves.
    for (int t = tid; t < WIN * 4; t += 64) {
        int row = t >> 2, g = t & 3;
        int n = (row0 + row / 7) * WW + cp0 + (row % 7);
        const __half* base = qkvh + ((size_t)(b * NN + n)) * C3 + col0 + g * 8;
        uint4 kr = *(const uint4*)(base + CC);
        uint4 vr = *(const uint4*)(base + 2 * CC);
        const __half2* k2 = (const __half2*)&kr;
        const __half2* v2 = (const __half2*)&vr;
        #pragma unroll
        for (int e = 0; e < 4; e++) {
            float2 kf = __half22float2(k2[e]);
            float2 vf = __half22float2(v2[e]);
            ks[row][g * 8 + e * 2 + 0] = kf.x;
            ks[row][g * 8 + e * 2 + 1] = kf.y;
            vs[row][g * 8 + e * 2 + 0] = vf.x;
            vs[row][g * 8 + e * 2 + 1] = vf.y;
        }
    }
    // 9x9 v halo as fp16 (zero-padded outside image)
    for (int t = tid; t < 81 * 4; t += 64) {
        int pix = t >> 2, g = t & 3;
        int r = row0 - 1 + pix / 9;
        int c = cp0 - 1 + pix % 9;
        uint4 vr = make_uint4(0, 0, 0, 0);
        if ((unsigned)r < (unsigned)HH && (unsigned)c < (unsigned)WW) {
            int n = r * WW + c;
            vr = *(const uint4*)(qkvh + ((size_t)(b * NN + n)) * C3 + 2 * CC + col0 + g * 8);
        }
        const __half2* v2 = (const __half2*)&vr;
        #pragma unroll
        for (int e = 0; e < 4; e++) vh[pix][g * 4 + e] = v2[e];
    }
    // conv weights + bias for this head
    for (int t = tid; t < 9 * HD; t += 64)
        wcs[t / HD][t % HD] = w_conv[(t / HD) * CC + col0 + (t % HD)];
    if (tid < HD) bcs[tid] = b_conv[col0 + tid];

    const int i = tid;
    const bool active = (i < WIN);
    int n_i = 0;
    float q[HD];
    if (active) {
        n_i = (row0 + i / 7) * WW + cp0 + (i % 7);
        const __half* p = qkvh + ((size_t)(b * NN + n_i)) * C3 + col0;
        #pragma unroll
        for (int g = 0; g < 4; g++) {
            uint4 qr4 = *(const uint4*)(p + g * 8);
            const __half2* q2 = (const __half2*)&qr4;
            #pragma unroll
            for (int e = 0; e < 4; e++) {
                float2 qf = __half22float2(q2[e]);
                q[g * 8 + e * 2 + 0] = qf.x;
                q[g * 8 + e * 2 + 1] = qf.y;
            }
        }
    }
    __syncthreads();

    if (active) {
        const float scale = 0.17677669529663687f;  // 32^-0.5
        float m = -1e30f;
        #pragma unroll 4
        for (int j = 0; j < WIN; j++) {
            float acc = 0.f;
            #pragma unroll
            for (int c4 = 0; c4 < 8; c4++) {
                float4 kv = *(const float4*)&ks[j][c4 * 4];
                acc += q[c4 * 4 + 0] * kv.x + q[c4 * 4 + 1] * kv.y +
                       q[c4 * 4 + 2] * kv.z + q[c4 * 4 + 3] * kv.w;
            }
            acc *= scale;
            S[i][j] = acc;
            m = fmaxf(m, acc);
        }
        float sum = 0.f;
        #pragma unroll 4
        for (int j = 0; j < WIN; j++) {
            float e = __expf(S[i][j] - m);
            sum += e;
            S[i][j] = e;
        }
        const float inv = 1.f / sum;

        float o[HD];
        #pragma unroll
        for (int d = 0; d < HD; d++) o[d] = bcs[d];   // start with conv bias
        #pragma unroll 4
        for (int j = 0; j < WIN; j++) {
            float pj = S[i][j] * inv;
            #pragma unroll
            for (int c4 = 0; c4 < 8; c4++) {
                float4 vv = *(const float4*)&vs[j][c4 * 4];
                o[c4 * 4 + 0] += pj * vv.x; o[c4 * 4 + 1] += pj * vv.y;
                o[c4 * 4 + 2] += pj * vv.z; o[c4 * 4 + 3] += pj * vv.w;
            }
        }

        // depthwise 3x3 conv from the halo (window pixel (r,c))
        const int r = i / 7, c = i % 7;
        #pragma unroll
        for (int kh = 0; kh < 3; kh++) {
            #pragma unroll
            for (int kw = 0; kw < 3; kw++) {
                const int pix = (r + kh) * 9 + (c + kw);
                const float* wc = wcs[kh * 3 + kw];
                #pragma unroll
                for (int c2 = 0; c2 < 16; c2++) {
                    float2 vf = __half22float2(vh[pix][c2]);
                    o[c2 * 2 + 0] += vf.x * wc[c2 * 2 + 0];
                    o[c2 * 2 + 1] += vf.y * wc[c2 * 2 + 1];
                }
            }
        }

        __half* yo = yh + ((size_t)(b * NN + n_i)) * CC + col0;
        #pragma unroll
        for (int c2 = 0; c2 < 16; c2++)
            ((__half2*)yo)[c2] = __floats2half2_rn(o[c2 * 2], o[c2 * 2 + 1]);
    }
}

// ---------------------------------------------------------------------------
extern "C" void kernel_launch(void* const* d_in, const int* in_sizes, int n_in,
                              void* d_out, int out_size)
{
    const float* x      = (const float*)d_in[0];
    const float* w_qkv  = (const float*)d_in[1];
    const float* w_proj = (const float*)d_in[2];
    const float* b_proj = (const float*)d_in[3];
    const float* w_conv = (const float*)d_in[4];
    const float* b_conv = (const float*)d_in[5];
    float* out = (float*)d_out;

    __half *qkvh_p, *xh_p, *yh_p, *wt1_p, *wt2_p;
    cudaGetSymbolAddress((void**)&qkvh_p, g_qkvh);
    cudaGetSymbolAddress((void**)&xh_p, g_xh);
    cudaGetSymbolAddress((void**)&yh_p, g_yh);
    cudaGetSymbolAddress((void**)&wt1_p, g_wt1);
    cudaGetSymbolAddress((void**)&wt2_p, g_wt2);

    const int gemm_smem = NSTAGE * STAGE_BYTES;  // 81920
    cudaFuncSetAttribute(gemm_f16_kernel<true>,
                         cudaFuncAttributeMaxDynamicSharedMemorySize, gemm_smem);
    cudaFuncSetAttribute(gemm_f16_kernel<false>,
                         cudaFuncAttributeMaxDynamicSharedMemorySize, gemm_smem);

    // 0) fp16 conversions
    {
        int n4 = MROWS * CC / 4;
        to_half_kernel<<<(n4 + 255) / 256, 256>>>(x, xh_p, n4);
        transpose_half_kernel<<<(CC * C3 + 255) / 256, 256>>>(w_qkv, wt1_p, CC, C3);
        transpose_half_kernel<<<(CC * CC + 255) / 256, 256>>>(w_proj, wt2_p, CC, CC);
    }
    // 1) qkvh = x @ w_qkv  (fp16 out)
    {
        dim3 grid(C3 / BN, MROWS / BM);
        gemm_f16_kernel<true><<<grid, 256, gemm_smem>>>(xh_p, wt1_p, qkvh_p, nullptr,
                                                        MROWS, C3, CC);
    }
    // 2) fused windowed attention + depthwise conv -> yh (fp16)
    attn_conv_kernel<<<BATCH * 64 * NHEADS, 64>>>(qkvh_p, w_conv, b_conv, yh_p);
    // 3) out = yh @ w_proj + b_proj (fp32 out)
    {
        dim3 grid(CC / BN, MROWS / BM);
        gemm_f16_kernel<false><<<grid, 256, gemm_smem>>>(yh_p, wt2_p, out, b_proj,
                                                         MROWS, CC, CC);
    }
}

// round 10
// speedup vs baseline: 2.1615x; 1.0833x over previous
#include <cuda_runtime.h>
#include <cuda_fp16.h>
#include <cstdint>

// Problem constants
#define BATCH 16
#define HH 56
#define WW 56
#define NN (HH * WW)          // 3136
#define CC 384
#define C3 (3 * CC)           // 1152
#define NHEADS 12
#define HD 32
#define WSZ 7
#define WIN 49
#define MROWS (BATCH * NN)    // 50176

// GEMM tiling (fp16 path)
#define BM 128
#define BN 128
#define BK 32
#define SROWH 40                  // smem row stride in halves (80B, conflict-free)
#define ABUF (BM * SROWH * 2)     // 10240 bytes per buffer
#define STAGE_BYTES (2 * ABUF)    // 20480
#define NSTAGE 4

// Attention smem geometry: per head Q,K,V tiles of 64 rows x 80B
#define ATILE 5120                // 64 * 80
#define AHEAD (3 * ATILE)         // 15360
#define ASMEM (4 * AHEAD)         // 61440

// Scratch (allocation-free rule: __device__ globals)
__device__ __half g_qkvh[(size_t)MROWS * C3];   // 115.5 MB
__device__ __half g_xh[(size_t)MROWS * CC];     // 38.5 MB
__device__ __half g_yh[(size_t)MROWS * CC];     // 38.5 MB
__device__ __half g_wt1[(size_t)C3 * CC];       // w_qkv^T fp16
__device__ __half g_wt2[(size_t)CC * CC];       // w_proj^T fp16

// ---------------------------------------------------------------------------
__device__ __forceinline__ uint32_t smem_u32(const void* p) {
    uint32_t a;
    asm("{ .reg .u64 t; cvta.to.shared.u64 t, %1; cvt.u32.u64 %0, t; }" : "=r"(a) : "l"(p));
    return a;
}
__device__ __forceinline__ void cp_async16(uint32_t saddr, const void* gaddr) {
    asm volatile("cp.async.cg.shared.global [%0], [%1], 16;" :: "r"(saddr), "l"(gaddr));
}
template <int N>
__device__ __forceinline__ void cp_wait() {
    asm volatile("cp.async.wait_group %0;" :: "n"(N) : "memory");
}
__device__ __forceinline__ void mma_f16(float c[4], const uint32_t a[4],
                                        uint32_t b0, uint32_t b1) {
    asm volatile(
        "mma.sync.aligned.m16n8k16.row.col.f32.f16.f16.f32 "
        "{%0,%1,%2,%3}, {%4,%5,%6,%7}, {%8,%9}, {%0,%1,%2,%3};"
        : "+f"(c[0]), "+f"(c[1]), "+f"(c[2]), "+f"(c[3])
        : "r"(a[0]), "r"(a[1]), "r"(a[2]), "r"(a[3]), "r"(b0), "r"(b1));
}
__device__ __forceinline__ void ldm_x4(uint32_t r[4], uint32_t addr) {
    asm volatile("ldmatrix.sync.aligned.m8n8.x4.shared.b16 {%0,%1,%2,%3}, [%4];"
        : "=r"(r[0]), "=r"(r[1]), "=r"(r[2]), "=r"(r[3]) : "r"(addr));
}
__device__ __forceinline__ void ldm_x4_t(uint32_t r[4], uint32_t addr) {
    asm volatile("ldmatrix.sync.aligned.m8n8.x4.trans.shared.b16 {%0,%1,%2,%3}, [%4];"
        : "=r"(r[0]), "=r"(r[1]), "=r"(r[2]), "=r"(r[3]) : "r"(addr));
}
__device__ __forceinline__ uint32_t h2u(__half2 h) {
    return *reinterpret_cast<uint32_t*>(&h);
}

// ---------------------------------------------------------------------------
// fp16 mma.sync GEMM (unchanged from R7): C = A @ Bt^T (+bias for fp32 out)
// ---------------------------------------------------------------------------
template <bool HALF_OUT>
__global__ __launch_bounds__(256, 2)
void gemm_f16_kernel(const __half* __restrict__ A, const __half* __restrict__ Bt,
                     void* __restrict__ Cout, const float* __restrict__ bias,
                     int M, int N, int K)
{
    extern __shared__ char smem[];
    const uint32_t sbase = smem_u32(smem);

    const int tid  = threadIdx.x;
    const int wid  = tid >> 5;
    const int lane = tid & 31;
    const int wm = (wid & 1) * 64;
    const int wn = (wid >> 1) * 32;
    const int qr = lane >> 2;
    const int qc = lane & 3;

    const int nbase = blockIdx.x * BN;
    const size_t mbase = (size_t)blockIdx.y * BM;

    const int row_ld = tid >> 1;
    const int c2_ld  = (tid & 1) << 1;

    const int r8  = lane & 7;
    const int sel = lane >> 3;
    const uint32_t rowadd = (uint32_t)((sel & 1) << 3);
    const uint32_t kbadd  = (uint32_t)((sel >> 1) << 4);
    uint32_t a_off[4], b_off[2];
    #pragma unroll
    for (int i = 0; i < 4; i++)
        a_off[i] = (uint32_t)(wm + 16 * i + rowadd + r8) * (SROWH * 2) + kbadd;
    #pragma unroll
    for (int p = 0; p < 2; p++)
        b_off[p] = (uint32_t)ABUF
                 + (uint32_t)(wn + 16 * p + rowadd + r8) * (SROWH * 2) + kbadd;

    float acc[4][4][4];
    #pragma unroll
    for (int i = 0; i < 4; i++)
        #pragma unroll
        for (int j = 0; j < 4; j++)
            #pragma unroll
            for (int t = 0; t < 4; t++) acc[i][j][t] = 0.f;

    const int nstages = K / BK;

    auto load_stage = [&](int s) {
        const uint32_t base = sbase + (uint32_t)(s % NSTAGE) * STAGE_BYTES;
        const int k0 = s * BK;
        const __half* Ag = A + (mbase + row_ld) * (size_t)K + k0;
        const __half* Bg = Bt + (size_t)(nbase + row_ld) * K + k0;
        const uint32_t soff = (uint32_t)row_ld * (SROWH * 2);
        #pragma unroll
        for (int cc = 0; cc < 2; cc++) {
            const int ch = c2_ld + cc;
            cp_async16(base + soff + ((uint32_t)ch << 4), Ag + (ch << 3));
            cp_async16(base + ABUF + soff + ((uint32_t)ch << 4), Bg + (ch << 3));
        }
        asm volatile("cp.async.commit_group;");
    };

    load_stage(0);
    load_stage(1);
    load_stage(2);

    for (int s = 0; s < nstages; s++) {
        if      (s + 2 < nstages) cp_wait<2>();
        else if (s + 1 < nstages) cp_wait<1>();
        else                      cp_wait<0>();
        __syncthreads();
        if (s + 3 < nstages) load_stage(s + 3);

        const uint32_t sstage = sbase + (uint32_t)(s % NSTAGE) * STAGE_BYTES;
        #pragma unroll
        for (int ks = 0; ks < 2; ks++) {
            const uint32_t kb = (uint32_t)ks << 5;
            uint32_t afr[4][4];
            uint32_t bfr[2][4];
            #pragma unroll
            for (int i = 0; i < 4; i++) ldm_x4(afr[i], sstage + a_off[i] + kb);
            #pragma unroll
            for (int p = 0; p < 2; p++) ldm_x4(bfr[p], sstage + b_off[p] + kb);
            #pragma unroll
            for (int i = 0; i < 4; i++)
                #pragma unroll
                for (int j = 0; j < 4; j++)
                    mma_f16(acc[i][j], afr[i], bfr[j >> 1][j & 1],
                            bfr[j >> 1][(j & 1) + 2]);
        }
    }

    #pragma unroll
    for (int i = 0; i < 4; i++) {
        const size_t row = mbase + wm + i * 16 + qr;
        #pragma unroll
        for (int j = 0; j < 4; j++) {
            const int col = nbase + wn + j * 8 + 2 * qc;
            if (HALF_OUT) {
                __half* Ch = (__half*)Cout;
                *(__half2*)(Ch + row * (size_t)N + col) =
                    __floats2half2_rn(acc[i][j][0], acc[i][j][1]);
                *(__half2*)(Ch + (row + 8) * (size_t)N + col) =
                    __floats2half2_rn(acc[i][j][2], acc[i][j][3]);
            } else {
                float* Cf = (float*)Cout;
                float2 v0 = make_float2(acc[i][j][0], acc[i][j][1]);
                float2 v1 = make_float2(acc[i][j][2], acc[i][j][3]);
                if (bias) {
                    float2 bb = *(const float2*)(bias + col);
                    v0.x += bb.x; v0.y += bb.y;
                    v1.x += bb.x; v1.y += bb.y;
                }
                *(float2*)(Cf + row * (size_t)N + col) = v0;
                *(float2*)(Cf + (row + 8) * (size_t)N + col) = v1;
            }
        }
    }
}

// ---------------------------------------------------------------------------
__global__ void to_half_kernel(const float* __restrict__ in, __half* __restrict__ out, int n4)
{
    int i = blockIdx.x * blockDim.x + threadIdx.x;
    if (i >= n4) return;
    float4 v = ((const float4*)in)[i];
    ((__half2*)out)[i * 2 + 0] = __floats2half2_rn(v.x, v.y);
    ((__half2*)out)[i * 2 + 1] = __floats2half2_rn(v.z, v.w);
}

__global__ void transpose_half_kernel(const float* __restrict__ in, __half* __restrict__ out,
                                      int K, int N)
{
    int i = blockIdx.x * blockDim.x + threadIdx.x;
    if (i >= K * N) return;
    int n = i % N, k = i / N;
    out[(size_t)n * K + k] = __float2half_rn(in[(size_t)k * N + n]);
}

// ---------------------------------------------------------------------------
// Tensor-core windowed attention. Block = (b, window, headgroup of 4),
// 128 threads, warp w handles head hg*4+w. fp16 MMA, fp32 accum/softmax.
// ---------------------------------------------------------------------------
__global__ __launch_bounds__(128)
void attn_tc_kernel(const __half* __restrict__ qkvh, __half* __restrict__ yh)
{
    extern __shared__ char sm[];
    const uint32_t sbase = smem_u32(sm);
    const int tid  = threadIdx.x;
    const int wid  = tid >> 5;
    const int lane = tid & 31;
    const int qr = lane >> 2, qc = lane & 3;
    const int r8 = lane & 7, g = lane >> 3;

    int blk = blockIdx.x;
    const int hg = blk % 3; blk /= 3;
    const int w = blk & 63; const int b = blk >> 6;
    const int row0 = (w >> 3) * 7, cpix0 = (w & 7) * 7;
    const int col0 = (hg * 4 + wid) * HD;

    // Zero pad rows 49..63 (first 64B of each 80B row), 12 tensor tiles
    {
        const uint4 z = make_uint4(0, 0, 0, 0);
        for (int t = tid; t < 720; t += 128) {
            int c = t & 3, r = (t >> 2) % 15, zt = t / 60;  // zt = head*3+tensor
            *(uint4*)(sm + zt * ATILE + (49 + r) * 80 + c * 16) = z;
        }
    }
    // Load q,k,v windows for 4 heads: 2352 16B chunks
    for (int it = 0; it < 19; it++) {
        int idx = tid + it * 128;
        if (idx < 2352) {
            int c = idx & 3;
            int r = (idx >> 2) % 49;
            int zt = (idx >> 2) / 49;          // head*3 + tensor
            int hh = zt / 3, tz = zt % 3;
            int pix = (row0 + r / 7) * WW + cpix0 + (r % 7);
            const __half* src = qkvh + ((size_t)(b * NN + pix)) * C3
                              + tz * CC + (hg * 4 + hh) * HD + c * 8;
            cp_async16(sbase + (uint32_t)(zt * ATILE + r * 80 + c * 16), src);
        }
    }
    asm volatile("cp.async.commit_group;");
    cp_wait<0>();
    __syncthreads();

    const uint32_t QB = sbase + (uint32_t)(wid * AHEAD);
    const uint32_t KB = QB + ATILE;
    const uint32_t VB = QB + 2 * ATILE;

    // K fragments: Kf[jtile 0..7][kstep 0..1] = {b0,b1}
    uint32_t Kf[8][2][2];
    #pragma unroll
    for (int up = 0; up < 4; up++)
        #pragma unroll
        for (int s = 0; s < 2; s++) {
            uint32_t addr = KB + (uint32_t)(16 * up + r8 + ((g & 1) << 3)) * 80u
                          + (uint32_t)(32 * s + ((g >> 1) << 4));
            uint32_t r[4];
            ldm_x4(r, addr);
            Kf[2 * up][s][0] = r[0]; Kf[2 * up][s][1] = r[2];
            Kf[2 * up + 1][s][0] = r[1]; Kf[2 * up + 1][s][1] = r[3];
        }
    // V fragments (trans): Vf[chantile 0..3][kstep j 0..3] = {b0,b1}
    uint32_t Vf[4][4][2];
    #pragma unroll
    for (int wk = 0; wk < 4; wk++)
        #pragma unroll
        for (int up = 0; up < 2; up++) {
            uint32_t addr = VB + (uint32_t)(16 * wk + r8 + ((g >> 1) << 3)) * 80u
                          + (uint32_t)(32 * up + ((g & 1) << 4));
            uint32_t r[4];
            ldm_x4_t(r, addr);
            Vf[2 * up][wk][0] = r[0]; Vf[2 * up][wk][1] = r[2];
            Vf[2 * up + 1][wk][0] = r[1]; Vf[2 * up + 1][wk][1] = r[3];
        }

    // col validity per n-tile (for this lane)
    bool vc0[7], vc1[7];
    #pragma unroll
    for (int u = 0; u < 7; u++) {
        int cb = 8 * u + 2 * qc;
        vc0[u] = cb < WIN;
        vc1[u] = cb + 1 < WIN;
    }

    const float scale = 0.17677669529663687f;  // 32^-0.5

    #pragma unroll
    for (int t = 0; t < 4; t++) {
        // Q fragments for this m-tile
        uint32_t Qf[2][4];
        #pragma unroll
        for (int s = 0; s < 2; s++) {
            uint32_t addr = QB + (uint32_t)(16 * t + r8 + ((g & 1) << 3)) * 80u
                          + (uint32_t)(32 * s + ((g >> 1) << 4));
            ldm_x4(Qf[s], addr);
        }
        // S = Q @ K^T (n-tiles 0..6; tile 7 entirely masked)
        float S[7][4];
        #pragma unroll
        for (int u = 0; u < 7; u++) {
            S[u][0] = S[u][1] = S[u][2] = S[u][3] = 0.f;
            mma_f16(S[u], Qf[0], Kf[u][0][0], Kf[u][0][1]);
            mma_f16(S[u], Qf[1], Kf[u][1][0], Kf[u][1][1]);
        }

        const int rr0 = 16 * t + qr;
        const int rr1 = rr0 + 8;
        const bool vr0 = rr0 < WIN, vr1 = rr1 < WIN;

        // row max over valid cols
        float m0 = -1e30f, m1 = -1e30f;
        #pragma unroll
        for (int u = 0; u < 7; u++) {
            if (vc0[u]) { m0 = fmaxf(m0, S[u][0]); m1 = fmaxf(m1, S[u][2]); }
            if (vc1[u]) { m0 = fmaxf(m0, S[u][1]); m1 = fmaxf(m1, S[u][3]); }
        }
        #pragma unroll
        for (int o = 1; o <= 2; o <<= 1) {
            m0 = fmaxf(m0, __shfl_xor_sync(0xffffffffu, m0, o));
            m1 = fmaxf(m1, __shfl_xor_sync(0xffffffffu, m1, o));
        }

        // P = exp(scale*(S-m)), masked; fp16 A-fragments
        uint32_t P[8][2];
        P[7][0] = 0u; P[7][1] = 0u;
        float sum0 = 0.f, sum1 = 0.f;
        #pragma unroll
        for (int u = 0; u < 7; u++) {
            float p0 = 0.f, p1 = 0.f, p2 = 0.f, p3 = 0.f;
            if (vr0) {
                if (vc0[u]) p0 = __expf((S[u][0] - m0) * scale);
                if (vc1[u]) p1 = __expf((S[u][1] - m0) * scale);
            }
            if (vr1) {
                if (vc0[u]) p2 = __expf((S[u][2] - m1) * scale);
                if (vc1[u]) p3 = __expf((S[u][3] - m1) * scale);
            }
            sum0 += p0 + p1;
            sum1 += p2 + p3;
            P[u][0] = h2u(__floats2half2_rn(p0, p1));
            P[u][1] = h2u(__floats2half2_rn(p2, p3));
        }
        #pragma unroll
        for (int o = 1; o <= 2; o <<= 1) {
            sum0 += __shfl_xor_sync(0xffffffffu, sum0, o);
            sum1 += __shfl_xor_sync(0xffffffffu, sum1, o);
        }
        const float is0 = vr0 ? 1.f / sum0 : 0.f;
        const float is1 = vr1 ? 1.f / sum1 : 0.f;

        // O = P @ V
        float O[4][4];
        #pragma unroll
        for (int u = 0; u < 4; u++)
            O[u][0] = O[u][1] = O[u][2] = O[u][3] = 0.f;
        #pragma unroll
        for (int wk = 0; wk < 4; wk++) {
            uint32_t afr[4] = { P[2 * wk][0], P[2 * wk][1],
                                P[2 * wk + 1][0], P[2 * wk + 1][1] };
            #pragma unroll
            for (int u = 0; u < 4; u++)
                mma_f16(O[u], afr, Vf[u][wk][0], Vf[u][wk][1]);
        }

        // write normalized output
        if (vr0) {
            int pix = (row0 + rr0 / 7) * WW + cpix0 + (rr0 % 7);
            __half* base = yh + ((size_t)(b * NN + pix)) * CC + col0;
            #pragma unroll
            for (int u = 0; u < 4; u++)
                *(__half2*)(base + 8 * u + 2 * qc) =
                    __floats2half2_rn(O[u][0] * is0, O[u][1] * is0);
        }
        if (vr1) {
            int pix = (row0 + rr1 / 7) * WW + cpix0 + (rr1 % 7);
            __half* base = yh + ((size_t)(b * NN + pix)) * CC + col0;
            #pragma unroll
            for (int u = 0; u < 4; u++)
                *(__half2*)(base + 8 * u + 2 * qc) =
                    __floats2half2_rn(O[u][2] * is1, O[u][3] * is1);
        }
    }
}

// ---------------------------------------------------------------------------
// Depthwise 3x3 conv on v (fp16) + bias, accumulated into yh (fp16 rmw).
// Thread = (b, pixel, 8-channel group).
// ---------------------------------------------------------------------------
__global__ __launch_bounds__(256)
void conv_add_h_kernel(const __half* __restrict__ qkvh,
                       const float* __restrict__ w_conv,
                       const float* __restrict__ b_conv,
                       __half* __restrict__ yh)
{
    const int CG = CC / 8;  // 48
    int idx = blockIdx.x * blockDim.x + threadIdx.x;
    if (idx >= BATCH * NN * CG) return;
    int cg = idx % CG;
    int n = (idx / CG) % NN;
    int b = idx / (CG * NN);
    int hh = n / WW, ww = n % WW;
    const int c = cg * 8;

    float acc[8];
    #pragma unroll
    for (int e = 0; e < 8; e++) acc[e] = b_conv[c + e];

    #pragma unroll
    for (int kh = 0; kh < 3; kh++) {
        int hn = hh + kh - 1;
        if ((unsigned)hn >= (unsigned)HH) continue;
        #pragma unroll
        for (int kw = 0; kw < 3; kw++) {
            int wn = ww + kw - 1;
            if ((unsigned)wn >= (unsigned)WW) continue;
            uint4 vr = *(const uint4*)(qkvh + ((size_t)(b * NN + hn * WW + wn)) * C3
                                       + 2 * CC + c);
            const __half2* v2 = (const __half2*)&vr;
            const float* wc = w_conv + (kh * 3 + kw) * CC + c;
            #pragma unroll
            for (int e = 0; e < 4; e++) {
                float2 vf = __half22float2(v2[e]);
                acc[e * 2 + 0] += vf.x * wc[e * 2 + 0];
                acc[e * 2 + 1] += vf.y * wc[e * 2 + 1];
            }
        }
    }

    __half* yo = yh + ((size_t)(b * NN + n)) * CC + c;
    uint4 yv = *(uint4*)yo;
    __half2* y2 = (__half2*)&yv;
    #pragma unroll
    for (int e = 0; e < 4; e++) {
        float2 yf = __half22float2(y2[e]);
        y2[e] = __floats2half2_rn(yf.x + acc[e * 2], yf.y + acc[e * 2 + 1]);
    }
    *(uint4*)yo = yv;
}

// ---------------------------------------------------------------------------
extern "C" void kernel_launch(void* const* d_in, const int* in_sizes, int n_in,
                              void* d_out, int out_size)
{
    const float* x      = (const float*)d_in[0];
    const float* w_qkv  = (const float*)d_in[1];
    const float* w_proj = (const float*)d_in[2];
    const float* b_proj = (const float*)d_in[3];
    const float* w_conv = (const float*)d_in[4];
    const float* b_conv = (const float*)d_in[5];
    float* out = (float*)d_out;

    __half *qkvh_p, *xh_p, *yh_p, *wt1_p, *wt2_p;
    cudaGetSymbolAddress((void**)&qkvh_p, g_qkvh);
    cudaGetSymbolAddress((void**)&xh_p, g_xh);
    cudaGetSymbolAddress((void**)&yh_p, g_yh);
    cudaGetSymbolAddress((void**)&wt1_p, g_wt1);
    cudaGetSymbolAddress((void**)&wt2_p, g_wt2);

    const int gemm_smem = NSTAGE * STAGE_BYTES;  // 81920
    cudaFuncSetAttribute(gemm_f16_kernel<true>,
                         cudaFuncAttributeMaxDynamicSharedMemorySize, gemm_smem);
    cudaFuncSetAttribute(gemm_f16_kernel<false>,
                         cudaFuncAttributeMaxDynamicSharedMemorySize, gemm_smem);
    cudaFuncSetAttribute(attn_tc_kernel,
                         cudaFuncAttributeMaxDynamicSharedMemorySize, ASMEM);

    // 0) fp16 conversions
    {
        int n4 = MROWS * CC / 4;
        to_half_kernel<<<(n4 + 255) / 256, 256>>>(x, xh_p, n4);
        transpose_half_kernel<<<(CC * C3 + 255) / 256, 256>>>(w_qkv, wt1_p, CC, C3);
        transpose_half_kernel<<<(CC * CC + 255) / 256, 256>>>(w_proj, wt2_p, CC, CC);
    }
    // 1) qkvh = x @ w_qkv (fp16 out)
    {
        dim3 grid(C3 / BN, MROWS / BM);
        gemm_f16_kernel<true><<<grid, 256, gemm_smem>>>(xh_p, wt1_p, qkvh_p, nullptr,
                                                        MROWS, C3, CC);
    }
    // 2) tensor-core windowed attention -> yh (fp16)
    attn_tc_kernel<<<BATCH * 64 * 3, 128, ASMEM>>>(qkvh_p, yh_p);
    // 3) yh += depthwise conv3x3(v) + b_conv
    {
        int total = BATCH * NN * (CC / 8);
        conv_add_h_kernel<<<(total + 255) / 256, 256>>>(qkvh_p, w_conv, b_conv, yh_p);
    }
    // 4) out = yh @ w_proj + b_proj (fp32 out)
    {
        dim3 grid(CC / BN, MROWS / BM);
        gemm_f16_kernel<false><<<grid, 256, gemm_smem>>>(yh_p, wt2_p, out, b_proj,
                                                         MROWS, CC, CC);
    }
}